// round 2
// baseline (speedup 1.0000x reference)
#include <cuda_runtime.h>

// Fused per-batch kernel, 256 threads/CTA, 2 CTAs/SM:
//   phase 1: h[t,:] = W1 @ x[b,t,:]        (f32x2 FMA, W1 rows in registers)
//   phase 2: 96 independent stateful material chains, in place in SMEM
//   phase 3: out[b,t,:] = softplus(W2) @ ys (f32x2 FMA, l split 4-way + shfl reduce)

typedef unsigned long long u64;

#define NTHREADS 256
#define TT 64
#define NTILES 16
#define BPAD 257
#define WPAD 20   // SW2 row stride (floats): 80B -> l-quarters hit disjoint bank groups

__device__ __forceinline__ u64 ffma2(u64 a, u64 b, u64 c) {
    u64 d; asm("fma.rn.f32x2 %0, %1, %2, %3;" : "=l"(d) : "l"(a), "l"(b), "l"(c)); return d;
}
__device__ __forceinline__ u64 addf2(u64 a, u64 b) {
    u64 d; asm("add.rn.f32x2 %0, %1, %2;" : "=l"(d) : "l"(a), "l"(b)); return d;
}
__device__ __forceinline__ u64 pack2(float a, float b) {
    u64 r; asm("mov.b64 %0, {%1, %2};" : "=l"(r) : "f"(a), "f"(b)); return r;
}
__device__ __forceinline__ u64 dup2(float a) {
    u64 r; asm("mov.b64 %0, {%1, %1};" : "=l"(r) : "f"(a)); return r;
}
__device__ __forceinline__ float2 unpack2(u64 v) {
    float2 r; asm("mov.b64 {%0, %1}, %2;" : "=f"(r.x), "=f"(r.y) : "l"(v)); return r;
}
__device__ __forceinline__ u64 lo64(const float4& v) { return pack2(v.x, v.y); }
__device__ __forceinline__ u64 hi64(const float4& v) { return pack2(v.z, v.w); }

__global__ void __launch_bounds__(NTHREADS, 2)
fused_fea_kernel(const float* __restrict__ x, const float* __restrict__ W1,
                 const float* __restrict__ W2, float* __restrict__ out)
{
    extern __shared__ float sm[];
    float* SW2s = sm;                       // 256 * WPAD floats, [l][o] padded
    float* xsd  = sm + 256 * WPAD;          // 2048 floats, x tile duplicated
    float* buf  = sm + 256 * WPAD + 2048;   // TT * BPAD floats, h -> ys in place

    const int tid = threadIdx.x;
    const int b   = blockIdx.x;

    // Stage softplus(W2), transposed + padded.
    for (int i = tid; i < 4096; i += NTHREADS) {
        int o = i >> 8, l = i & 255;
        SW2s[l * WPAD + o] = log1pf(expf(W2[i]));
    }

    // W1 rows for this thread's two output lanes (l = lp, lp+128), packed f32x2.
    const int lp = tid & 127;
    u64 w1r[16];
    {
        const float4* r0 = (const float4*)(W1 + lp * 16);
        const float4* r1 = (const float4*)(W1 + (lp + 128) * 16);
#pragma unroll
        for (int k = 0; k < 4; ++k) {
            float4 a = r0[k], bb = r1[k];
            w1r[4 * k + 0] = pack2(a.x, bb.x);
            w1r[4 * k + 1] = pack2(a.y, bb.y);
            w1r[4 * k + 2] = pack2(a.z, bb.z);
            w1r[4 * k + 3] = pack2(a.w, bb.w);
        }
    }
    __syncthreads();

    // Material constants (match reference float32 values).
    const float NUv    = 0.3f;
    const float CEL00  = 200.0f / 0.91f;
    const float CEL01  = CEL00 * 0.3f;
    const float CEL22  = CEL00 * 0.35f;
    const float INV_E  = 1.0f / 200.0f;
    const float INV_G  = 2.6f / 200.0f;
    const float GMOD   = 200.0f / 2.6f;
    const float SY0    = 2.0f, HARD = 10.0f;
    const float INV3GH = 1.0f / (3.0f * GMOD + HARD);
    const float KPEN   = 50.0f;
    const float D0     = 0.1f, DFm = 0.9f;

    // Per-thread material state (threads 0..63 bulk, 64..95 cohesive).
    float ep1 = 0.f, ep2 = 0.f, ep12 = 0.f, epbar = 0.f, hist = 0.f;

    const float* xb = x   + (size_t)b * (1024 * 16);
    float*       ob = out + (size_t)b * (1024 * 16);

    const int th = tid >> 7;          // phase-1 timestep half
    const int t3 = tid >> 2;          // phase-3 timestep
    const int q3 = tid & 3;           // phase-3 l-quarter

    for (int tile = 0; tile < NTILES; ++tile) {
        const int t0 = tile * TT;

        // Stage x tile, duplicated (one float4 load + two float4 stores per thread).
        {
            float4 v = ((const float4*)(xb + t0 * 16))[tid];
            float4* xd = (float4*)xsd + 2 * tid;
            xd[0] = make_float4(v.x, v.x, v.y, v.y);
            xd[1] = make_float4(v.z, v.z, v.w, v.w);
        }
        __syncthreads();

        // ---- Phase 1: h tile = W1 @ x (each thread: 2 channels x 32 timesteps) ----
        for (int tg = 0; tg < 8; ++tg) {
            const int tq = th * 8 + tg;                    // 4-timestep group
            const float4* xr = ((const float4*)xsd) + tq * 32;
            u64 a0 = 0, a1 = 0, a2 = 0, a3 = 0;
#pragma unroll
            for (int f2 = 0; f2 < 8; ++f2) {
                float4 v0 = xr[f2], v1 = xr[8 + f2], v2 = xr[16 + f2], v3 = xr[24 + f2];
                a0 = ffma2(w1r[2 * f2],     lo64(v0), a0);
                a0 = ffma2(w1r[2 * f2 + 1], hi64(v0), a0);
                a1 = ffma2(w1r[2 * f2],     lo64(v1), a1);
                a1 = ffma2(w1r[2 * f2 + 1], hi64(v1), a1);
                a2 = ffma2(w1r[2 * f2],     lo64(v2), a2);
                a2 = ffma2(w1r[2 * f2 + 1], hi64(v2), a2);
                a3 = ffma2(w1r[2 * f2],     lo64(v3), a3);
                a3 = ffma2(w1r[2 * f2 + 1], hi64(v3), a3);
            }
            const int t = tq * 4;
            float2 h0 = unpack2(a0), h1 = unpack2(a1), h2 = unpack2(a2), h3 = unpack2(a3);
            buf[(t + 0) * BPAD + lp] = h0.x;  buf[(t + 0) * BPAD + lp + 128] = h0.y;
            buf[(t + 1) * BPAD + lp] = h1.x;  buf[(t + 1) * BPAD + lp + 128] = h1.y;
            buf[(t + 2) * BPAD + lp] = h2.x;  buf[(t + 2) * BPAD + lp + 128] = h2.y;
            buf[(t + 3) * BPAD + lp] = h3.x;  buf[(t + 3) * BPAD + lp + 128] = h3.y;
        }
        __syncthreads();

        // ---- Phase 2: sequential material update (in place) ----
        if (tid < 64) {
            float* p = buf + tid * 3;
            for (int t = 0; t < TT; ++t, p += BPAD) {
                float e1 = p[0], e2 = p[1], e12 = p[2];
                float d1 = e1 - ep1, d2 = e2 - ep2, d12 = e12 - ep12;
                float s1  = CEL00 * d1 + CEL01 * d2;
                float s2  = CEL01 * d1 + CEL00 * d2;
                float s12 = CEL22 * d12;
                float qv  = fmaxf(s1 * s1 - s1 * s2 + s2 * s2 + 3.0f * s12 * s12, 1e-12f);
                float seq = __fsqrt_rn(qv);
                float fy  = seq - (SY0 + HARD * epbar);
                if (fy > 0.0f) {
                    float dep = fy * INV3GH;
                    epbar += dep;
                    float r = __fdiv_rn(SY0 + HARD * epbar, seq);
                    s1 *= r; s2 *= r; s12 *= r;
                    ep1  = e1  - (s1 - NUv * s2) * INV_E;
                    ep2  = e2  - (s2 - NUv * s1) * INV_E;
                    ep12 = e12 - s12 * INV_G;
                }
                p[0] = s1; p[1] = s2; p[2] = s12;
            }
        } else if (tid < 96) {
            float* p = buf + 192 + (tid - 64) * 2;
            for (int t = 0; t < TT; ++t, p += BPAD) {
                float dn = p[0], ds = p[1];
                float dnp = fmaxf(dn, 0.0f);
                float lam = __fsqrt_rn(fmaxf(dnp * dnp + ds * ds, 1e-12f));
                hist = fmaxf(hist, lam);
                float dmg = __fdiv_rn(hist - D0, fmaxf(hist, 1e-12f) * DFm);
                dmg = fminf(fmaxf(dmg, 0.0f), 1.0f);
                float omd = 1.0f - dmg;
                p[0] = KPEN * dn * (dn > 0.0f ? omd : 1.0f);
                p[1] = omd * KPEN * ds;
            }
        }
        __syncthreads();

        // ---- Phase 3: out = softplus(W2) @ ys ----
        // Thread owns timestep t3 and l-quarter q3 (l = q3 + 4i); 8 packed accumulators
        // cover all 16 outputs. Butterfly-reduce across the 4 quarters.
        {
            u64 acc[8] = {0, 0, 0, 0, 0, 0, 0, 0};
            const float* yrow = buf + t3 * BPAD + q3;
#pragma unroll 4
            for (int i = 0; i < 64; ++i) {
                u64 yd = dup2(yrow[4 * i]);
                const float4* wp = (const float4*)(SW2s + (q3 + 4 * i) * WPAD);
                float4 wa = wp[0], wb = wp[1], wc = wp[2], wd = wp[3];
                acc[0] = ffma2(lo64(wa), yd, acc[0]);
                acc[1] = ffma2(hi64(wa), yd, acc[1]);
                acc[2] = ffma2(lo64(wb), yd, acc[2]);
                acc[3] = ffma2(hi64(wb), yd, acc[3]);
                acc[4] = ffma2(lo64(wc), yd, acc[4]);
                acc[5] = ffma2(hi64(wc), yd, acc[5]);
                acc[6] = ffma2(lo64(wd), yd, acc[6]);
                acc[7] = ffma2(hi64(wd), yd, acc[7]);
            }
#pragma unroll
            for (int k = 0; k < 8; ++k) {
                acc[k] = addf2(acc[k], __shfl_xor_sync(0xffffffffu, acc[k], 1));
                acc[k] = addf2(acc[k], __shfl_xor_sync(0xffffffffu, acc[k], 2));
            }
            if (q3 == 0) {
                float2* og = (float2*)(ob + (size_t)(t0 + t3) * 16);
#pragma unroll
                for (int k = 0; k < 8; ++k) og[k] = unpack2(acc[k]);
            }
        }
        __syncthreads();   // buf/xsd reused next tile
    }
}

extern "C" void kernel_launch(void* const* d_in, const int* in_sizes, int n_in,
                              void* d_out, int out_size)
{
    const float* x  = (const float*)d_in[0];
    const float* W1 = (const float*)d_in[1];
    const float* W2 = (const float*)d_in[2];
    float* out = (float*)d_out;

    const size_t smem = (size_t)(256 * WPAD + 2048 + TT * BPAD) * sizeof(float); // 94464 B
    cudaFuncSetAttribute(fused_fea_kernel, cudaFuncAttributeMaxDynamicSharedMemorySize, (int)smem);
    fused_fea_kernel<<<256, NTHREADS, smem>>>(x, W1, W2, out);
}

// round 3
// speedup vs baseline: 1.2893x; 1.2893x over previous
#include <cuda_runtime.h>

// Fused per-batch kernel, 256 threads/CTA, 2 CTAs/SM.
//   phase 1: h = W1 @ x      (4 channels/thread in regs -> FMA:LDS = 2:1)
//   phase 2: 96 stateful material chains in SMEM (MUFU-based, short chain)
//   phase 3: out = softplus(W2) @ ys (l interleaved 4-way, conflict-free banks)

typedef unsigned long long u64;

#define NTHREADS 256
#define TT 64
#define NTILES 16
#define BPAD 260   // == 4 (mod 32): phase-3 y loads hit 32 distinct banks
#define WPAD 20    // SW2 row stride; q3-interleaved float4 loads are conflict-free

__device__ __forceinline__ u64 ffma2(u64 a, u64 b, u64 c) {
    u64 d; asm("fma.rn.f32x2 %0, %1, %2, %3;" : "=l"(d) : "l"(a), "l"(b), "l"(c)); return d;
}
__device__ __forceinline__ u64 addf2(u64 a, u64 b) {
    u64 d; asm("add.rn.f32x2 %0, %1, %2;" : "=l"(d) : "l"(a), "l"(b)); return d;
}
__device__ __forceinline__ u64 pack2(float a, float b) {
    u64 r; asm("mov.b64 %0, {%1, %2};" : "=l"(r) : "f"(a), "f"(b)); return r;
}
__device__ __forceinline__ u64 dup2(float a) {
    u64 r; asm("mov.b64 %0, {%1, %1};" : "=l"(r) : "f"(a)); return r;
}
__device__ __forceinline__ float2 unpack2(u64 v) {
    float2 r; asm("mov.b64 {%0, %1}, %2;" : "=f"(r.x), "=f"(r.y) : "l"(v)); return r;
}
__device__ __forceinline__ u64 lo64(const float4& v) { return pack2(v.x, v.y); }
__device__ __forceinline__ u64 hi64(const float4& v) { return pack2(v.z, v.w); }

__global__ void __launch_bounds__(NTHREADS, 2)
fused_fea_kernel(const float* __restrict__ x, const float* __restrict__ W1,
                 const float* __restrict__ W2, float* __restrict__ out)
{
    extern __shared__ float sm[];
    float* SW2s = sm;                       // 256*WPAD floats, softplus(W2) [l][o] padded
    float* xsd  = sm + 256 * WPAD;          // 2048 floats, x tile, every value duplicated
    float* buf  = sm + 256 * WPAD + 2048;   // TT*BPAD floats, h -> ys in place

    const int tid = threadIdx.x;
    const int b   = blockIdx.x;

    // Stage softplus(W2), transposed + padded.
    for (int i = tid; i < 4096; i += NTHREADS) {
        int o = i >> 8, l = i & 255;
        SW2s[l * WPAD + o] = log1pf(expf(W2[i]));
    }

    // Phase-1 ownership: lq = tid&63 owns channels lq, lq+64, lq+128, lq+192
    // as packed pairs A=(lq, lq+128), B=(lq+64, lq+192); tq = tid>>6 owns 16 timesteps.
    const int lq = tid & 63;
    const int tq = tid >> 6;
    u64 wA[16], wB[16];
    {
        const float4* rA0 = (const float4*)(W1 + lq * 16);
        const float4* rA1 = (const float4*)(W1 + (lq + 128) * 16);
        const float4* rB0 = (const float4*)(W1 + (lq + 64) * 16);
        const float4* rB1 = (const float4*)(W1 + (lq + 192) * 16);
#pragma unroll
        for (int k = 0; k < 4; ++k) {
            float4 a0 = rA0[k], a1 = rA1[k], b0 = rB0[k], b1 = rB1[k];
            wA[4*k+0] = pack2(a0.x, a1.x); wA[4*k+1] = pack2(a0.y, a1.y);
            wA[4*k+2] = pack2(a0.z, a1.z); wA[4*k+3] = pack2(a0.w, a1.w);
            wB[4*k+0] = pack2(b0.x, b1.x); wB[4*k+1] = pack2(b0.y, b1.y);
            wB[4*k+2] = pack2(b0.z, b1.z); wB[4*k+3] = pack2(b0.w, b1.w);
        }
    }
    __syncthreads();

    // Material constants (reference float32 values).
    const float NUv    = 0.3f;
    const float CEL00  = 200.0f / 0.91f;
    const float CEL01  = CEL00 * 0.3f;
    const float CEL22  = CEL00 * 0.35f;
    const float INV_E  = 1.0f / 200.0f;
    const float INV_G  = 2.6f / 200.0f;
    const float GMOD   = 200.0f / 2.6f;
    const float SY0    = 2.0f, HARD = 10.0f;
    const float INV3GH = 1.0f / (3.0f * GMOD + HARD);
    const float KPEN   = 50.0f;
    const float D0     = 0.1f, INV_DFm = 1.0f / 0.9f;

    float ep1 = 0.f, ep2 = 0.f, ep12 = 0.f, epbar = 0.f, hist = 0.f;

    const float* xb = x   + (size_t)b * (1024 * 16);
    float*       ob = out + (size_t)b * (1024 * 16);

    const int t3 = tid >> 2;   // phase-3 timestep
    const int q3 = tid & 3;    // phase-3 l-interleave class

    for (int tile = 0; tile < NTILES; ++tile) {
        const int t0 = tile * TT;

        // Stage x tile, duplicated (one float4 load, two float4 stores per thread).
        {
            float4 v = ((const float4*)(xb + t0 * 16))[tid];
            float4* xd = (float4*)xsd + 2 * tid;
            xd[0] = make_float4(v.x, v.x, v.y, v.y);
            xd[1] = make_float4(v.z, v.z, v.w, v.w);
        }
        __syncthreads();

        // ---- Phase 1: 4 channels x 16 timesteps per thread, 2 timesteps in flight ----
        {
            const u64* xq = (const u64*)xsd;
#pragma unroll
            for (int tp = 0; tp < 8; ++tp) {
                const int t = tq * 16 + tp * 2;
                const u64* x0 = xq + t * 16;
                u64 aA0 = 0, aB0 = 0, aA1 = 0, aB1 = 0;
#pragma unroll
                for (int f = 0; f < 16; ++f) {
                    u64 v0 = x0[f], v1 = x0[16 + f];
                    aA0 = ffma2(wA[f], v0, aA0);
                    aB0 = ffma2(wB[f], v0, aB0);
                    aA1 = ffma2(wA[f], v1, aA1);
                    aB1 = ffma2(wB[f], v1, aB1);
                }
                float2 hA0 = unpack2(aA0), hB0 = unpack2(aB0);
                float2 hA1 = unpack2(aA1), hB1 = unpack2(aB1);
                float* r0 = buf + t * BPAD + lq;
                float* r1 = r0 + BPAD;
                r0[0] = hA0.x; r0[128] = hA0.y; r0[64] = hB0.x; r0[192] = hB0.y;
                r1[0] = hA1.x; r1[128] = hA1.y; r1[64] = hB1.x; r1[192] = hB1.y;
            }
        }
        __syncthreads();

        // ---- Phase 2: sequential material update (in place) ----
        if (tid < 64) {
            float* p = buf + tid * 3;
            for (int t = 0; t < TT; ++t, p += BPAD) {
                float e1 = p[0], e2 = p[1], e12 = p[2];
                float d1 = e1 - ep1, d2 = e2 - ep2, d12 = e12 - ep12;
                float s1  = CEL00 * d1 + CEL01 * d2;
                float s2  = CEL01 * d1 + CEL00 * d2;
                float s12 = CEL22 * d12;
                float qv  = fmaxf(s1 * s1 - s1 * s2 + s2 * s2 + 3.0f * s12 * s12, 1e-12f);
                float rs  = rsqrtf(qv);          // MUFU.RSQ
                float seq = qv * rs;             // sqrt(qv)
                float ynow = SY0 + HARD * epbar;
                float fy  = seq - ynow;
                if (fy > 0.0f) {
                    epbar += fy * INV3GH;
                    float r = (SY0 + HARD * epbar) * rs;  // y_new / seq
                    s1 *= r; s2 *= r; s12 *= r;
                    ep1  = e1  - (s1 - NUv * s2) * INV_E;
                    ep2  = e2  - (s2 - NUv * s1) * INV_E;
                    ep12 = e12 - s12 * INV_G;
                }
                p[0] = s1; p[1] = s2; p[2] = s12;
            }
        } else if (tid < 96) {
            float* p = buf + 192 + (tid - 64) * 2;
            for (int t = 0; t < TT; ++t, p += BPAD) {
                float dn = p[0], ds = p[1];
                float dnp = fmaxf(dn, 0.0f);
                float q2  = fmaxf(dnp * dnp + ds * ds, 1e-12f);
                float lam = q2 * rsqrtf(q2);
                hist = fmaxf(hist, lam);
                float dmg = __fdividef(hist - D0, hist) * INV_DFm;
                dmg = fminf(fmaxf(dmg, 0.0f), 1.0f);
                float omd = 1.0f - dmg;
                p[0] = KPEN * dn * (dn > 0.0f ? omd : 1.0f);
                p[1] = omd * KPEN * ds;
            }
        }
        __syncthreads();

        // ---- Phase 3: out = softplus(W2) @ ys ----
        // Thread (t3, q3): timestep t3, l = 4i + q3; 16 outputs in 8 packed accs;
        // butterfly-reduce across the 4 q3 classes.
        {
            u64 acc[8] = {0, 0, 0, 0, 0, 0, 0, 0};
            const float* yrow = buf + t3 * BPAD + q3;
#pragma unroll 8
            for (int i = 0; i < 64; ++i) {
                u64 yd = dup2(yrow[4 * i]);
                const float4* wp = (const float4*)(SW2s + (4 * i + q3) * WPAD);
                float4 wa = wp[0], wb2 = wp[1], wc = wp[2], wd = wp[3];
                acc[0] = ffma2(lo64(wa),  yd, acc[0]);
                acc[1] = ffma2(hi64(wa),  yd, acc[1]);
                acc[2] = ffma2(lo64(wb2), yd, acc[2]);
                acc[3] = ffma2(hi64(wb2), yd, acc[3]);
                acc[4] = ffma2(lo64(wc),  yd, acc[4]);
                acc[5] = ffma2(hi64(wc),  yd, acc[5]);
                acc[6] = ffma2(lo64(wd),  yd, acc[6]);
                acc[7] = ffma2(hi64(wd),  yd, acc[7]);
            }
#pragma unroll
            for (int k = 0; k < 8; ++k) {
                acc[k] = addf2(acc[k], __shfl_xor_sync(0xffffffffu, acc[k], 1));
                acc[k] = addf2(acc[k], __shfl_xor_sync(0xffffffffu, acc[k], 2));
            }
            if (q3 == 0) {
                float2* og = (float2*)(ob + (size_t)(t0 + t3) * 16);
#pragma unroll
                for (int k = 0; k < 8; ++k) og[k] = unpack2(acc[k]);
            }
        }
        __syncthreads();   // buf/xsd reused next tile
    }
}

extern "C" void kernel_launch(void* const* d_in, const int* in_sizes, int n_in,
                              void* d_out, int out_size)
{
    const float* x  = (const float*)d_in[0];
    const float* W1 = (const float*)d_in[1];
    const float* W2 = (const float*)d_in[2];
    float* out = (float*)d_out;

    const size_t smem = (size_t)(256 * WPAD + 2048 + TT * BPAD) * sizeof(float); // 95232 B
    cudaFuncSetAttribute(fused_fea_kernel, cudaFuncAttributeMaxDynamicSharedMemorySize, (int)smem);
    fused_fea_kernel<<<256, NTHREADS, smem>>>(x, W1, W2, out);
}

// round 4
// speedup vs baseline: 1.5971x; 1.2387x over previous
#include <cuda_runtime.h>

// Warp-specialized pipeline, 256 threads/CTA, 2 CTAs/SM, one CTA per batch.
//   Warps 0-3 (G, tid 0-127): P1 (fc1) and P3 (fc2) GEMMs, f32x2 packed FMA.
//   Warps 4-6 (S, tid 128-223): 96 sequential material chains (P2).
//   Warp 7   (tid 224-255): stages x tiles global->shared.
// Tiles of TT=32 timesteps, double-buffered: P2(k) overlaps P3(k-1)+P1(k+1).

typedef unsigned long long u64;

#define NTHREADS 256
#define TT 32
#define NTILES 32
#define BPAD 260   // buf row stride: ==4 (mod 32) -> P3 y-loads conflict-free
#define WPAD 20    // SW2 row stride: 80B, 16B-aligned, q3-classes disjoint
#define XPAD 36    // x-tile row stride (duplicated): 144B, 16B-aligned, low-conflict

__device__ __forceinline__ u64 ffma2(u64 a, u64 b, u64 c) {
    u64 d; asm("fma.rn.f32x2 %0, %1, %2, %3;" : "=l"(d) : "l"(a), "l"(b), "l"(c)); return d;
}
__device__ __forceinline__ u64 addf2(u64 a, u64 b) {
    u64 d; asm("add.rn.f32x2 %0, %1, %2;" : "=l"(d) : "l"(a), "l"(b)); return d;
}
__device__ __forceinline__ u64 pack2(float a, float b) {
    u64 r; asm("mov.b64 %0, {%1, %2};" : "=l"(r) : "f"(a), "f"(b)); return r;
}
__device__ __forceinline__ u64 dup2(float a) {
    u64 r; asm("mov.b64 %0, {%1, %1};" : "=l"(r) : "f"(a)); return r;
}
__device__ __forceinline__ float2 unpack2(u64 v) {
    float2 r; asm("mov.b64 {%0, %1}, %2;" : "=f"(r.x), "=f"(r.y) : "l"(v)); return r;
}

__global__ void __launch_bounds__(NTHREADS, 2)
fused_fea_kernel(const float* __restrict__ x, const float* __restrict__ W1,
                 const float* __restrict__ W2, float* __restrict__ out)
{
    extern __shared__ float sm[];
    float* SW2s = sm;                          // 256*WPAD floats
    float* xsd  = sm + 256 * WPAD;             // 2 * TT*XPAD floats (duplicated x)
    float* buf  = xsd + 2 * TT * XPAD;         // 2 * TT*BPAD floats (h -> ys)

    const int tid = threadIdx.x;
    const int b   = blockIdx.x;
    const bool isG = (tid < 128);

    const float* xb = x   + (size_t)b * (1024 * 16);
    float*       ob = out + (size_t)b * (1024 * 16);

    // ---- Prologue: stage softplus(W2); warp 7 stages x tiles 0 and 1 ----
    for (int i = tid; i < 4096; i += NTHREADS) {
        int o = i >> 8, l = i & 255;
        SW2s[l * WPAD + o] = log1pf(expf(W2[i]));
    }
    if (tid >= 224) {
        const int j = tid - 224;                  // 0..31, one timestep each
#pragma unroll
        for (int tile = 0; tile < 2; ++tile) {
            const float4* src = (const float4*)(xb + tile * (TT * 16) + j * 16);
            float* dst = xsd + tile * (TT * XPAD) + j * XPAD;
#pragma unroll
            for (int m = 0; m < 4; ++m) {
                float4 v = src[m];
                ((float4*)dst)[2 * m]     = make_float4(v.x, v.x, v.y, v.y);
                ((float4*)dst)[2 * m + 1] = make_float4(v.z, v.z, v.w, v.w);
            }
        }
    }

    // G: W1 rows in registers. lq = tid&63 owns channels lq,+64,+128,+192 as
    // packed pairs A=(lq,lq+128), B=(lq+64,lq+192); tq = tid>>6 owns 16 timesteps.
    const int lq = tid & 63;
    const int tq = (tid >> 6) & 1;
    u64 wA[16], wB[16];
    if (isG) {
        const float4* rA0 = (const float4*)(W1 + lq * 16);
        const float4* rA1 = (const float4*)(W1 + (lq + 128) * 16);
        const float4* rB0 = (const float4*)(W1 + (lq + 64) * 16);
        const float4* rB1 = (const float4*)(W1 + (lq + 192) * 16);
#pragma unroll
        for (int k = 0; k < 4; ++k) {
            float4 a0 = rA0[k], a1 = rA1[k], b0 = rB0[k], b1 = rB1[k];
            wA[4*k+0] = pack2(a0.x, a1.x); wA[4*k+1] = pack2(a0.y, a1.y);
            wA[4*k+2] = pack2(a0.z, a1.z); wA[4*k+3] = pack2(a0.w, a1.w);
            wB[4*k+0] = pack2(b0.x, b1.x); wB[4*k+1] = pack2(b0.y, b1.y);
            wB[4*k+2] = pack2(b0.z, b1.z); wB[4*k+3] = pack2(b0.w, b1.w);
        }
    }

    // Material constants.
    const float NUv    = 0.3f;
    const float CEL00  = 200.0f / 0.91f;
    const float CEL01  = CEL00 * 0.3f;
    const float CEL22  = CEL00 * 0.35f;
    const float INV_E  = 1.0f / 200.0f;
    const float INV_G  = 2.6f / 200.0f;
    const float GMOD   = 200.0f / 2.6f;
    const float SY0    = 2.0f, HARD = 10.0f;
    const float INV3GH = 1.0f / (3.0f * GMOD + HARD);
    const float KPEN   = 50.0f;
    const float D0     = 0.1f, INV_DFm = 1.0f / 0.9f;

    float ep1 = 0.f, ep2 = 0.f, ep12 = 0.f, epbar = 0.f, hist = 0.f;
    const int s = tid - 128;   // scan-point index for S warps 4-6

    const int t3 = (tid >> 2) & 31;  // P3 timestep
    const int q3 = tid & 3;          // P3 l-interleave class

    __syncthreads();

    // ---- Fill: P1(0) ----
    if (isG) {
        float* bufb = buf;           // buffer 0
        const float* xsb = xsd;      // x tile 0
#pragma unroll
        for (int tp = 0; tp < 8; ++tp) {
            const int t = tq * 16 + 2 * tp;
            const ulonglong2* x0 = (const ulonglong2*)(xsb + t * XPAD);
            const ulonglong2* x1 = (const ulonglong2*)(xsb + (t + 1) * XPAD);
            u64 aA0 = 0, aB0 = 0, aA1 = 0, aB1 = 0;
#pragma unroll
            for (int f4 = 0; f4 < 8; ++f4) {
                ulonglong2 u = x0[f4], v = x1[f4];
                aA0 = ffma2(wA[2*f4], u.x, aA0); aA0 = ffma2(wA[2*f4+1], u.y, aA0);
                aB0 = ffma2(wB[2*f4], u.x, aB0); aB0 = ffma2(wB[2*f4+1], u.y, aB0);
                aA1 = ffma2(wA[2*f4], v.x, aA1); aA1 = ffma2(wA[2*f4+1], v.y, aA1);
                aB1 = ffma2(wB[2*f4], v.x, aB1); aB1 = ffma2(wB[2*f4+1], v.y, aB1);
            }
            float2 hA0 = unpack2(aA0), hB0 = unpack2(aB0);
            float2 hA1 = unpack2(aA1), hB1 = unpack2(aB1);
            float* r0 = bufb + t * BPAD + lq;
            float* r1 = r0 + BPAD;
            r0[0] = hA0.x; r0[128] = hA0.y; r0[64] = hB0.x; r0[192] = hB0.y;
            r1[0] = hA1.x; r1[128] = hA1.y; r1[64] = hB1.x; r1[192] = hB1.y;
        }
    }
    __syncthreads();

    // ---- Pipelined slots ----
    for (int k = 0; k < NTILES; ++k) {
        if (isG) {
            // P3(k-1): out tile from ys in buf[(k-1)&1]
            if (k >= 1) {
                const float* bufb = buf + ((k - 1) & 1) * (TT * BPAD);
                u64 acc[8] = {0,0,0,0,0,0,0,0};
                const float* yrow = bufb + t3 * BPAD + q3;
#pragma unroll 8
                for (int i = 0; i < 64; ++i) {
                    u64 yd = dup2(yrow[4 * i]);
                    const ulonglong2* wp = (const ulonglong2*)(SW2s + (4 * i + q3) * WPAD);
                    ulonglong2 wa = wp[0], wb = wp[1], wc = wp[2], wd = wp[3];
                    acc[0] = ffma2(wa.x, yd, acc[0]);
                    acc[1] = ffma2(wa.y, yd, acc[1]);
                    acc[2] = ffma2(wb.x, yd, acc[2]);
                    acc[3] = ffma2(wb.y, yd, acc[3]);
                    acc[4] = ffma2(wc.x, yd, acc[4]);
                    acc[5] = ffma2(wc.y, yd, acc[5]);
                    acc[6] = ffma2(wd.x, yd, acc[6]);
                    acc[7] = ffma2(wd.y, yd, acc[7]);
                }
#pragma unroll
                for (int m = 0; m < 8; ++m) {
                    acc[m] = addf2(acc[m], __shfl_xor_sync(0xffffffffu, acc[m], 1));
                    acc[m] = addf2(acc[m], __shfl_xor_sync(0xffffffffu, acc[m], 2));
                }
                if (q3 == 0) {
                    float2* og = (float2*)(ob + (size_t)((k - 1) * TT + t3) * 16);
#pragma unroll
                    for (int m = 0; m < 8; ++m) og[m] = unpack2(acc[m]);
                }
            }
            // G-only barrier: P3 reads of buf[(k-1)&1] complete before P1(k+1) overwrites it.
            asm volatile("bar.sync 1, 128;" ::: "memory");
            // P1(k+1) into buf[(k+1)&1]
            if (k + 1 < NTILES) {
                float* bufb = buf + ((k + 1) & 1) * (TT * BPAD);
                const float* xsb = xsd + ((k + 1) & 1) * (TT * XPAD);
#pragma unroll
                for (int tp = 0; tp < 8; ++tp) {
                    const int t = tq * 16 + 2 * tp;
                    const ulonglong2* x0 = (const ulonglong2*)(xsb + t * XPAD);
                    const ulonglong2* x1 = (const ulonglong2*)(xsb + (t + 1) * XPAD);
                    u64 aA0 = 0, aB0 = 0, aA1 = 0, aB1 = 0;
#pragma unroll
                    for (int f4 = 0; f4 < 8; ++f4) {
                        ulonglong2 u = x0[f4], v = x1[f4];
                        aA0 = ffma2(wA[2*f4], u.x, aA0); aA0 = ffma2(wA[2*f4+1], u.y, aA0);
                        aB0 = ffma2(wB[2*f4], u.x, aB0); aB0 = ffma2(wB[2*f4+1], u.y, aB0);
                        aA1 = ffma2(wA[2*f4], v.x, aA1); aA1 = ffma2(wA[2*f4+1], v.y, aA1);
                        aB1 = ffma2(wB[2*f4], v.x, aB1); aB1 = ffma2(wB[2*f4+1], v.y, aB1);
                    }
                    float2 hA0 = unpack2(aA0), hB0 = unpack2(aB0);
                    float2 hA1 = unpack2(aA1), hB1 = unpack2(aB1);
                    float* r0 = bufb + t * BPAD + lq;
                    float* r1 = r0 + BPAD;
                    r0[0] = hA0.x; r0[128] = hA0.y; r0[64] = hB0.x; r0[192] = hB0.y;
                    r1[0] = hA1.x; r1[128] = hA1.y; r1[64] = hB1.x; r1[192] = hB1.y;
                }
            }
        } else if (s < 64) {
            // P2 bulk: J2 radial return on buf[k&1]
            float* p = buf + (k & 1) * (TT * BPAD) + s * 3;
#pragma unroll 4
            for (int t = 0; t < TT; ++t, p += BPAD) {
                float e1 = p[0], e2 = p[1], e12 = p[2];
                float d1 = e1 - ep1, d2 = e2 - ep2, d12 = e12 - ep12;
                float s1  = CEL00 * d1 + CEL01 * d2;
                float s2  = CEL01 * d1 + CEL00 * d2;
                float s12 = CEL22 * d12;
                float qv  = fmaxf(s1 * s1 - s1 * s2 + s2 * s2 + 3.0f * s12 * s12, 1e-12f);
                float rs  = rsqrtf(qv);
                float seq = qv * rs;
                float fy  = seq - (SY0 + HARD * epbar);
                if (fy > 0.0f) {
                    epbar += fy * INV3GH;
                    float r = (SY0 + HARD * epbar) * rs;
                    s1 *= r; s2 *= r; s12 *= r;
                    ep1  = e1  - (s1 - NUv * s2) * INV_E;
                    ep2  = e2  - (s2 - NUv * s1) * INV_E;
                    ep12 = e12 - s12 * INV_G;
                }
                p[0] = s1; p[1] = s2; p[2] = s12;
            }
        } else if (s < 96) {
            // P2 cohesive: bilinear damage on buf[k&1]
            float* p = buf + (k & 1) * (TT * BPAD) + 192 + (s - 64) * 2;
#pragma unroll 4
            for (int t = 0; t < TT; ++t, p += BPAD) {
                float dn = p[0], ds = p[1];
                float dnp = fmaxf(dn, 0.0f);
                float q2  = fmaxf(dnp * dnp + ds * ds, 1e-12f);
                float lam = q2 * rsqrtf(q2);
                hist = fmaxf(hist, lam);
                float dmg = __fdividef(hist - D0, hist) * INV_DFm;
                dmg = fminf(fmaxf(dmg, 0.0f), 1.0f);
                float omd = 1.0f - dmg;
                p[0] = KPEN * dn * (dn > 0.0f ? omd : 1.0f);
                p[1] = omd * KPEN * ds;
            }
        } else {
            // Warp 7: stage x tile (k+2) into xsd[k&1]
            if (k + 2 < NTILES) {
                const int j = tid - 224;
                const float4* src = (const float4*)(xb + (k + 2) * (TT * 16) + j * 16);
                float* dst = xsd + (k & 1) * (TT * XPAD) + j * XPAD;
#pragma unroll
                for (int m = 0; m < 4; ++m) {
                    float4 v = src[m];
                    ((float4*)dst)[2 * m]     = make_float4(v.x, v.x, v.y, v.y);
                    ((float4*)dst)[2 * m + 1] = make_float4(v.z, v.z, v.w, v.w);
                }
            }
        }
        __syncthreads();
    }

    // ---- Drain: P3(31) ----
    if (isG) {
        const float* bufb = buf + ((NTILES - 1) & 1) * (TT * BPAD);
        u64 acc[8] = {0,0,0,0,0,0,0,0};
        const float* yrow = bufb + t3 * BPAD + q3;
#pragma unroll 8
        for (int i = 0; i < 64; ++i) {
            u64 yd = dup2(yrow[4 * i]);
            const ulonglong2* wp = (const ulonglong2*)(SW2s + (4 * i + q3) * WPAD);
            ulonglong2 wa = wp[0], wb = wp[1], wc = wp[2], wd = wp[3];
            acc[0] = ffma2(wa.x, yd, acc[0]);
            acc[1] = ffma2(wa.y, yd, acc[1]);
            acc[2] = ffma2(wb.x, yd, acc[2]);
            acc[3] = ffma2(wb.y, yd, acc[3]);
            acc[4] = ffma2(wc.x, yd, acc[4]);
            acc[5] = ffma2(wc.y, yd, acc[5]);
            acc[6] = ffma2(wd.x, yd, acc[6]);
            acc[7] = ffma2(wd.y, yd, acc[7]);
        }
#pragma unroll
        for (int m = 0; m < 8; ++m) {
            acc[m] = addf2(acc[m], __shfl_xor_sync(0xffffffffu, acc[m], 1));
            acc[m] = addf2(acc[m], __shfl_xor_sync(0xffffffffu, acc[m], 2));
        }
        if (q3 == 0) {
            float2* og = (float2*)(ob + (size_t)((NTILES - 1) * TT + t3) * 16);
#pragma unroll
            for (int m = 0; m < 8; ++m) og[m] = unpack2(acc[m]);
        }
    }
}

extern "C" void kernel_launch(void* const* d_in, const int* in_sizes, int n_in,
                              void* d_out, int out_size)
{
    const float* x  = (const float*)d_in[0];
    const float* W1 = (const float*)d_in[1];
    const float* W2 = (const float*)d_in[2];
    float* out = (float*)d_out;

    const size_t smem = (size_t)(256 * WPAD + 2 * TT * XPAD + 2 * TT * BPAD) * sizeof(float); // 96256 B
    cudaFuncSetAttribute(fused_fea_kernel, cudaFuncAttributeMaxDynamicSharedMemorySize, (int)smem);
    fused_fea_kernel<<<256, NTHREADS, smem>>>(x, W1, W2, out);
}